// round 6
// baseline (speedup 1.0000x reference)
#include <cuda_runtime.h>
#include <cuda_bf16.h>
#include <cstdint>
#include <math.h>

// Problem constants
#define BB 2
#define TT 2048
#define EE 1024
#define HH 16
#define DD 64
#define VV 32000
#define BT (BB * TT)   // 4096

// ---------------- scratch (device globals; no allocations allowed) ------------
__device__ float g_x[BT * EE];
__device__ float g_q[BT * EE];
__device__ float g_k[BT * EE];
__device__ float g_v[BT * EE];
__device__ float g_o[BT * EE];
__device__ float g_lterms[BT];

// ---------------- helpers -----------------------------------------------------
__device__ __forceinline__ uint32_t f2tf32(float f) {
    uint32_t u;
    asm("cvt.rna.tf32.f32 %0, %1;" : "=r"(u) : "f"(f));
    return u;
}

__device__ __forceinline__ void mma_tf32(float* d, const uint4& a, const uint2& b) {
    asm volatile(
        "mma.sync.aligned.m16n8k8.row.col.f32.tf32.tf32.f32 "
        "{%0,%1,%2,%3}, {%4,%5,%6,%7}, {%8,%9}, {%0,%1,%2,%3};"
        : "+f"(d[0]), "+f"(d[1]), "+f"(d[2]), "+f"(d[3])
        : "r"(a.x), "r"(a.y), "r"(a.z), "r"(a.w), "r"(b.x), "r"(b.y));
}

// ---------------- embedding: x = tok_table[tokens] + pos_emb ------------------
__global__ void embed_kernel(const int* __restrict__ tokens,
                             const float* __restrict__ tok_table,
                             const float* __restrict__ pos_emb,
                             float* __restrict__ x) {
    int idx = blockIdx.x * blockDim.x + threadIdx.x;  // over BT*EE
    int bt = idx >> 10;          // /EE
    int e  = idx & (EE - 1);
    int t  = bt & (TT - 1);      // bt % TT
    int tok = tokens[bt];
    x[idx] = tok_table[tok * EE + e] + pos_emb[t * EE + e];
}

// ============ mma.sync tf32 NT GEMM: C[m,n] = sum_k A[m,k]B[n,k] + bias[n] ====
// CTA tile 128x128, BK=32 (4 k-steps of 8). 256 threads, 8 warps (2x4),
// warp tile 64x32 = 4x4 m16n8k8 fragments. fp32 accumulate in registers.
// 2-stage smem pipeline, ONE __syncthreads per BK iteration:
//   at iter i: buf holds chunk i; STS chunk i+1 -> buf^1 and LDG chunk i+2
//   overlap the MMA reads from buf; sync at end of iter.

#define GM_BM 128
#define GM_BN 128
#define GM_BK 32
#define GM_BUF 4096     // floats per As or Bs buffer

__device__ __forceinline__ void gm_load_regs(const float* __restrict__ Aptr,
                                             const float* __restrict__ Bptr,
                                             int K, int k0, int tid,
                                             float4* pa, float4* pb) {
#pragma unroll
    for (int it = 0; it < 4; it++) {
        int q = tid + it * 256;
        int row = q >> 3, c = q & 7;
        pa[it] = *(const float4*)(Aptr + (size_t)row * K + k0 + c * 4);
        pb[it] = *(const float4*)(Bptr + (size_t)row * K + k0 + c * 4);
    }
}

__device__ __forceinline__ void gm_store_smem(float* __restrict__ As,
                                              float* __restrict__ Bs,
                                              const float4* pa, const float4* pb,
                                              int tid) {
#pragma unroll
    for (int it = 0; it < 4; it++) {
        int q = tid + it * 256;
        int row = q >> 3, c = q & 7;
        int ks = c >> 1, half = c & 1;
        // A scatter: [R=8][ks=4][lane=32][4]
        {
            int R = row >> 4, r16 = row & 15;
            int gA = r16 & 7, hi = r16 >> 3;
            int base = ((R * 4 + ks) * 32 + gA * 4) * 4 + half * 2 + hi;
            ((uint32_t*)As)[base + 0 * 4] = f2tf32(pa[it].x);
            ((uint32_t*)As)[base + 1 * 4] = f2tf32(pa[it].y);
            ((uint32_t*)As)[base + 2 * 4] = f2tf32(pa[it].z);
            ((uint32_t*)As)[base + 3 * 4] = f2tf32(pa[it].w);
        }
        // B scatter: [Nb=16][ks=4][lane=32][2]
        {
            int Nb = row >> 3, gn = row & 7;
            int base = ((Nb * 4 + ks) * 32 + gn * 4) * 2 + half;
            ((uint32_t*)Bs)[base + 0 * 2] = f2tf32(pb[it].x);
            ((uint32_t*)Bs)[base + 1 * 2] = f2tf32(pb[it].y);
            ((uint32_t*)Bs)[base + 2 * 2] = f2tf32(pb[it].z);
            ((uint32_t*)Bs)[base + 3 * 2] = f2tf32(pb[it].w);
        }
    }
}

__global__ __launch_bounds__(256) void gemm_mma(const float* __restrict__ A,
                                                const float* __restrict__ B,
                                                const float* __restrict__ bias,
                                                float* __restrict__ C,
                                                int M, int N, int K) {
    extern __shared__ float sm[];
    float* As = sm;            // [2][GM_BUF]
    float* Bs = sm + 2 * GM_BUF;

    int tid = threadIdx.x;
    int lane = tid & 31, wid = tid >> 5;
    int warp_m = wid >> 2, warp_n = wid & 3;
    int g = lane >> 2, t = lane & 3;

    int bm = blockIdx.x * GM_BM;
    int bn = blockIdx.y * GM_BN;

    const float* Aptr = A + (size_t)bm * K;
    const float* Bptr = B + (size_t)bn * K;

    float acc[4][4][4];
#pragma unroll
    for (int mi = 0; mi < 4; mi++)
#pragma unroll
        for (int ni = 0; ni < 4; ni++)
#pragma unroll
            for (int e = 0; e < 4; e++) acc[mi][ni][e] = 0.0f;

    const int NCH = K / GM_BK;
    int abase = warp_m * 4;    // R offset
    int bbase = warp_n * 4;    // Nb offset

    float4 pa[4], pb[4];
    // prologue: chunk 0 into buf0, chunk 1 into regs
    gm_load_regs(Aptr, Bptr, K, 0, tid, pa, pb);
    gm_store_smem(As, Bs, pa, pb, tid);
    if (NCH > 1) gm_load_regs(Aptr, Bptr, K, GM_BK, tid, pa, pb);
    __syncthreads();

    for (int i = 0; i < NCH; i++) {
        int buf = i & 1;
        float* An = As + (buf ^ 1) * GM_BUF;
        float* Bn = Bs + (buf ^ 1) * GM_BUF;

        // stage chunk i+1 into the other buffer (overlaps MMA reads from buf)
        if (i + 1 < NCH) gm_store_smem(An, Bn, pa, pb, tid);
        // start fetching chunk i+2
        if (i + 2 < NCH) gm_load_regs(Aptr, Bptr, K, (i + 2) * GM_BK, tid, pa, pb);

        const float* Ab = As + buf * GM_BUF;
        const float* Bb = Bs + buf * GM_BUF;
#pragma unroll
        for (int ks = 0; ks < 4; ks++) {
            uint4 af[4];
            uint2 bf[4];
#pragma unroll
            for (int mi = 0; mi < 4; mi++)
                af[mi] = *(const uint4*)&Ab[((abase + mi) * 4 + ks) * 128 + lane * 4];
#pragma unroll
            for (int ni = 0; ni < 4; ni++)
                bf[ni] = *(const uint2*)&Bb[((bbase + ni) * 4 + ks) * 64 + lane * 2];
#pragma unroll
            for (int mi = 0; mi < 4; mi++)
#pragma unroll
                for (int ni = 0; ni < 4; ni++)
                    mma_tf32(acc[mi][ni], af[mi], bf[ni]);
        }
        __syncthreads();
    }

    // epilogue: add bias, store (float2 per fragment row)
    int m_base = bm + warp_m * 64;
    int n_base = bn + warp_n * 32;
#pragma unroll
    for (int mi = 0; mi < 4; mi++) {
#pragma unroll
        for (int ni = 0; ni < 4; ni++) {
            int r0 = m_base + mi * 16 + g;
            int col = n_base + ni * 8 + t * 2;
            float b0 = __ldg(&bias[col]);
            float b1 = __ldg(&bias[col + 1]);
            float2 o0 = make_float2(acc[mi][ni][0] + b0, acc[mi][ni][1] + b1);
            float2 o1 = make_float2(acc[mi][ni][2] + b0, acc[mi][ni][3] + b1);
            *(float2*)&C[(size_t)r0 * N + col] = o0;
            *(float2*)&C[(size_t)(r0 + 8) * N + col] = o1;
        }
    }
}

// ---------------- causal attention (flash-style, online softmax) --------------
#define AT_TQ 16
#define AT_TS 64

__global__ __launch_bounds__(256) void attn_kernel(const float* __restrict__ q,
                                                   const float* __restrict__ k,
                                                   const float* __restrict__ v,
                                                   float* __restrict__ o) {
    int qt0 = blockIdx.x * AT_TQ;
    int h = blockIdx.y;
    int b = blockIdx.z;

    __shared__ float Qs[AT_TQ][DD + 1];
    __shared__ float Ks[AT_TS][DD + 1];
    __shared__ float Vs[AT_TS][DD + 1];
    __shared__ float Ps[AT_TQ][AT_TS + 1];
    __shared__ float m_s[AT_TQ], l_s[AT_TQ], alpha_s[AT_TQ];

    int tid = threadIdx.x;

    for (int i = tid; i < AT_TQ * DD; i += 256) {
        int r = i >> 6, d = i & 63;
        Qs[r][d] = q[(size_t)(b * TT + qt0 + r) * EE + h * DD + d];
    }
    if (tid < AT_TQ) { m_s[tid] = -1e30f; l_s[tid] = 0.0f; }
    __syncthreads();

    float o_acc[4] = {0.f, 0.f, 0.f, 0.f};
    int d_own = tid & 63;
    int r_base = (tid >> 6) * 4;

    int n_tiles = (qt0 + AT_TQ - 1) / AT_TS + 1;

    for (int kt = 0; kt < n_tiles; kt++) {
        int s0 = kt * AT_TS;
        for (int i = tid; i < AT_TS * DD; i += 256) {
            int r = i >> 6, d = i & 63;
            size_t gi = (size_t)(b * TT + s0 + r) * EE + h * DD + d;
            Ks[r][d] = k[gi];
            Vs[r][d] = v[gi];
        }
        __syncthreads();

        float sacc[4] = {0.f, 0.f, 0.f, 0.f};
#pragma unroll
        for (int d = 0; d < DD; d++) {
            float kv = Ks[d_own][d];
#pragma unroll
            for (int j = 0; j < 4; j++) sacc[j] = fmaf(Qs[r_base + j][d], kv, sacc[j]);
        }
        int s_glob = s0 + d_own;
#pragma unroll
        for (int j = 0; j < 4; j++) {
            int t_glob = qt0 + r_base + j;
            Ps[r_base + j][d_own] = (s_glob <= t_glob) ? sacc[j] : -1e30f;
        }
        __syncthreads();

        int warp = tid >> 5, lane = tid & 31;
#pragma unroll
        for (int rw = 0; rw < 2; rw++) {
            int rr = warp * 2 + rw;
            float x0 = Ps[rr][lane], x1 = Ps[rr][lane + 32];
            float mx = fmaxf(x0, x1);
#pragma unroll
            for (int off = 16; off; off >>= 1)
                mx = fmaxf(mx, __shfl_xor_sync(0xffffffffu, mx, off));
            float m_old = m_s[rr];
            float m_new = fmaxf(m_old, mx);
            float e0 = __expf(x0 - m_new);
            float e1 = __expf(x1 - m_new);
            float sum = e0 + e1;
#pragma unroll
            for (int off = 16; off; off >>= 1)
                sum += __shfl_xor_sync(0xffffffffu, sum, off);
            Ps[rr][lane] = e0;
            Ps[rr][lane + 32] = e1;
            if (lane == 0) {
                float alpha = __expf(m_old - m_new);
                alpha_s[rr] = alpha;
                l_s[rr] = l_s[rr] * alpha + sum;
                m_s[rr] = m_new;
            }
        }
        __syncthreads();

#pragma unroll
        for (int j = 0; j < 4; j++) o_acc[j] *= alpha_s[r_base + j];
#pragma unroll
        for (int s = 0; s < AT_TS; s++) {
            float vv = Vs[s][d_own];
#pragma unroll
            for (int j = 0; j < 4; j++) o_acc[j] = fmaf(Ps[r_base + j][s], vv, o_acc[j]);
        }
        __syncthreads();
    }

#pragma unroll
    for (int j = 0; j < 4; j++) {
        int r = r_base + j;
        o[(size_t)(b * TT + qt0 + r) * EE + h * DD + d_own] =
            o_acc[j] / l_s[r] * 0.125f;
    }
}

// ---------------- per-row logsumexp + per-row loss term -----------------------
__global__ __launch_bounds__(256) void lse_loss_kernel(const float* __restrict__ logits,
                                                       const int* __restrict__ targets,
                                                       float* __restrict__ lterms) {
    int row = blockIdx.x;
    const float* p = logits + (size_t)row * VV;
    float m = -1e30f, l = 0.0f;
    for (int i = threadIdx.x; i < VV; i += 256) {
        float x = p[i];
        if (x > m) { l = l * __expf(m - x) + 1.0f; m = x; }
        else       { l += __expf(x - m); }
    }
    __shared__ float ms[256], ls[256];
    ms[threadIdx.x] = m;
    ls[threadIdx.x] = l;
    __syncthreads();
    for (int s = 128; s; s >>= 1) {
        if (threadIdx.x < (unsigned)s) {
            float m2 = ms[threadIdx.x + s], l2 = ls[threadIdx.x + s];
            float M = fmaxf(ms[threadIdx.x], m2);
            ls[threadIdx.x] = ls[threadIdx.x] * __expf(ms[threadIdx.x] - M) + l2 * __expf(m2 - M);
            ms[threadIdx.x] = M;
        }
        __syncthreads();
    }
    if (threadIdx.x == 0) {
        float lse = ms[0] + logf(ls[0]);
        lterms[row] = lse - p[targets[row]];
    }
}

__global__ __launch_bounds__(256) void loss_reduce(const float* __restrict__ lterms,
                                                   float* __restrict__ out, int do_write) {
    __shared__ float s[256];
    float acc = 0.0f;
    for (int i = threadIdx.x; i < BT; i += 256) acc += lterms[i];
    s[threadIdx.x] = acc;
    __syncthreads();
    for (int st = 128; st; st >>= 1) {
        if (threadIdx.x < (unsigned)st) s[threadIdx.x] += s[threadIdx.x + st];
        __syncthreads();
    }
    if (threadIdx.x == 0 && do_write) out[0] = s[0] / (float)BT;
}

// ------------------------------- launch ---------------------------------------
#define GSM_BYTES (4 * GM_BUF * sizeof(float))   // 64KB dynamic smem

extern "C" void kernel_launch(void* const* d_in, const int* in_sizes, int n_in,
                              void* d_out, int out_size) {
    const int*   tokens    = (const int*)d_in[0];
    const int*   targets   = (const int*)d_in[1];
    const float* tok_table = (const float*)d_in[2];
    const float* pos_emb   = (const float*)d_in[3];
    const float* Wq        = (const float*)d_in[4];
    const float* bq        = (const float*)d_in[5];
    const float* Wk        = (const float*)d_in[6];
    const float* bk        = (const float*)d_in[7];
    const float* Wv        = (const float*)d_in[8];
    const float* bv        = (const float*)d_in[9];
    const float* Wo        = (const float*)d_in[10];
    const float* bo        = (const float*)d_in[11];
    float* out = (float*)d_out;

    float *x, *q, *k, *v, *o, *lt;
    cudaGetSymbolAddress((void**)&x,  g_x);
    cudaGetSymbolAddress((void**)&q,  g_q);
    cudaGetSymbolAddress((void**)&k,  g_k);
    cudaGetSymbolAddress((void**)&v,  g_v);
    cudaGetSymbolAddress((void**)&o,  g_o);
    cudaGetSymbolAddress((void**)&lt, g_lterms);

    static int smem_set = 0;
    if (!smem_set) {
        cudaFuncSetAttribute(gemm_mma, cudaFuncAttributeMaxDynamicSharedMemorySize,
                             (int)GSM_BYTES);
        smem_set = 1;
    }

    // 1) embedding
    embed_kernel<<<(BT * EE) / 256, 256>>>(tokens, tok_table, pos_emb, x);

    // 2) QKV projections (tf32 mma.sync NT gemms, N=E)
    dim3 gqkv(BT / GM_BM, EE / GM_BN);   // m fastest
    gemm_mma<<<gqkv, 256, GSM_BYTES>>>(x, Wq, bq, q, BT, EE, EE);
    gemm_mma<<<gqkv, 256, GSM_BYTES>>>(x, Wk, bk, k, BT, EE, EE);
    gemm_mma<<<gqkv, 256, GSM_BYTES>>>(x, Wv, bv, v, BT, EE, EE);

    // 3) causal attention
    attn_kernel<<<dim3(TT / AT_TQ, HH, BB), 256>>>(q, k, v, o);

    // 4) output projection -> logits straight into d_out
    dim3 glog(BT / GM_BM, VV / GM_BN);   // m fastest: Wo tile stays L2-resident
    gemm_mma<<<glog, 256, GSM_BYTES>>>(o, Wo, bo, out, BT, VV, EE);

    // 5) loss
    lse_loss_kernel<<<BT, 256>>>(out, targets, lt);
    int write_loss = (out_size > BT * VV) ? 1 : 0;
    loss_reduce<<<1, 256>>>(lt, out + (size_t)BT * VV, write_loss);
}

// round 8
// speedup vs baseline: 1.1400x; 1.1400x over previous
#include <cuda_runtime.h>
#include <cuda_bf16.h>
#include <cstdint>
#include <math.h>

// Problem constants
#define BB 2
#define TT 2048
#define EE 1024
#define HH 16
#define DD 64
#define VV 32000
#define BT (BB * TT)   // 4096

// ---------------- scratch (device globals; no allocations allowed) ------------
__device__ float g_x[BT * EE];
__device__ float g_q[BT * EE];
__device__ float g_k[BT * EE];
__device__ float g_v[BT * EE];
__device__ float g_o[BT * EE];
__device__ float g_lterms[BT];

// ---------------- helpers -----------------------------------------------------
__device__ __forceinline__ uint32_t f2tf32(float f) {
    uint32_t u;
    asm("cvt.rna.tf32.f32 %0, %1;" : "=r"(u) : "f"(f));
    return u;
}

__device__ __forceinline__ void mma_tf32(float* d, const uint4& a, const uint2& b) {
    asm volatile(
        "mma.sync.aligned.m16n8k8.row.col.f32.tf32.tf32.f32 "
        "{%0,%1,%2,%3}, {%4,%5,%6,%7}, {%8,%9}, {%0,%1,%2,%3};"
        : "+f"(d[0]), "+f"(d[1]), "+f"(d[2]), "+f"(d[3])
        : "r"(a.x), "r"(a.y), "r"(a.z), "r"(a.w), "r"(b.x), "r"(b.y));
}

// ---------------- embedding: x = tok_table[tokens] + pos_emb ------------------
__global__ void embed_kernel(const int* __restrict__ tokens,
                             const float* __restrict__ tok_table,
                             const float* __restrict__ pos_emb,
                             float* __restrict__ x) {
    int idx = blockIdx.x * blockDim.x + threadIdx.x;  // over BT*EE
    int bt = idx >> 10;          // /EE
    int e  = idx & (EE - 1);
    int t  = bt & (TT - 1);      // bt % TT
    int tok = tokens[bt];
    x[idx] = tok_table[tok * EE + e] + pos_emb[t * EE + e];
}

// ============ mma.sync tf32 NT GEMM: C[m,n] = sum_k A[m,k]B[n,k] + bias[n] ====
// CTA tile 128x128, BK=32 (4 k-steps of 8). 256 threads, 8 warps (2x4),
// warp tile 64x32 = 4x4 m16n8k8 fragments. fp32 accumulate in registers.
// 2 CTAs/SM (launch_bounds 256,2): staging goes through ONE float4[4] array
// (A then B sequentially) to keep regs <= 128.
//
// SMEM layouts (fragment-native, conflict-free):
//   As: [R=8 (16-row blk)][ks=4][lane=32][4]  Bs: [Nb=16 (8-col blk)][ks=4][lane=32][2]

#define GM_BM 128
#define GM_BN 128
#define GM_BK 32
#define GM_BUF 4096     // floats per As or Bs buffer

__device__ __forceinline__ void gm_ldg(const float* __restrict__ P, int K, int k0,
                                       int tid, float4* p) {
#pragma unroll
    for (int it = 0; it < 4; it++) {
        int q = tid + it * 256;
        int row = q >> 3, c = q & 7;
        p[it] = *(const float4*)(P + (size_t)row * K + k0 + c * 4);
    }
}

__device__ __forceinline__ void gm_stA(float* __restrict__ As, const float4* p, int tid) {
#pragma unroll
    for (int it = 0; it < 4; it++) {
        int q = tid + it * 256;
        int row = q >> 3, c = q & 7;
        int ks = c >> 1, half = c & 1;
        int R = row >> 4, r16 = row & 15;
        int gA = r16 & 7, hi = r16 >> 3;
        int base = ((R * 4 + ks) * 32 + gA * 4) * 4 + half * 2 + hi;
        ((uint32_t*)As)[base + 0 * 4] = f2tf32(p[it].x);
        ((uint32_t*)As)[base + 1 * 4] = f2tf32(p[it].y);
        ((uint32_t*)As)[base + 2 * 4] = f2tf32(p[it].z);
        ((uint32_t*)As)[base + 3 * 4] = f2tf32(p[it].w);
    }
}

__device__ __forceinline__ void gm_stB(float* __restrict__ Bs, const float4* p, int tid) {
#pragma unroll
    for (int it = 0; it < 4; it++) {
        int q = tid + it * 256;
        int row = q >> 3, c = q & 7;
        int ks = c >> 1, half = c & 1;
        int Nb = row >> 3, gn = row & 7;
        int base = ((Nb * 4 + ks) * 32 + gn * 4) * 2 + half;
        ((uint32_t*)Bs)[base + 0 * 2] = f2tf32(p[it].x);
        ((uint32_t*)Bs)[base + 1 * 2] = f2tf32(p[it].y);
        ((uint32_t*)Bs)[base + 2 * 2] = f2tf32(p[it].z);
        ((uint32_t*)Bs)[base + 3 * 2] = f2tf32(p[it].w);
    }
}

__global__ __launch_bounds__(256, 2) void gemm_mma(const float* __restrict__ A,
                                                   const float* __restrict__ B,
                                                   const float* __restrict__ bias,
                                                   float* __restrict__ C,
                                                   int M, int N, int K) {
    extern __shared__ float sm[];
    float* As = sm;            // [2][GM_BUF]
    float* Bs = sm + 2 * GM_BUF;

    int tid = threadIdx.x;
    int lane = tid & 31, wid = tid >> 5;
    int warp_m = wid >> 2, warp_n = wid & 3;
    int g = lane >> 2, t = lane & 3;

    int bm = blockIdx.x * GM_BM;
    int bn = blockIdx.y * GM_BN;

    const float* Aptr = A + (size_t)bm * K;
    const float* Bptr = B + (size_t)bn * K;

    float acc[4][4][4];
#pragma unroll
    for (int mi = 0; mi < 4; mi++)
#pragma unroll
        for (int ni = 0; ni < 4; ni++)
#pragma unroll
            for (int e = 0; e < 4; e++) acc[mi][ni][e] = 0.0f;

    const int NCH = K / GM_BK;
    int abase = warp_m * 4;    // R offset
    int bbase = warp_n * 4;    // Nb offset

    float4 st[4];              // single staging array (A then B)
    // prologue: chunk 0 into buf0
    gm_ldg(Aptr, K, 0, tid, st);     // A chunk 0
    gm_stA(As, st, tid);
    gm_ldg(Bptr, K, 0, tid, st);     // B chunk 0
    gm_stB(Bs, st, tid);
    __syncthreads();

    for (int i = 0; i < NCH; i++) {
        int buf = i & 1;
        float* An = As + (buf ^ 1) * GM_BUF;
        float* Bn = Bs + (buf ^ 1) * GM_BUF;
        const float* Ab = As + buf * GM_BUF;
        const float* Bb = Bs + buf * GM_BUF;
        bool stage = (i + 1 < NCH);
        int k1 = (i + 1) * GM_BK;

#pragma unroll
        for (int ks = 0; ks < 4; ks++) {
            uint4 af[4];
            uint2 bf[4];
#pragma unroll
            for (int mi = 0; mi < 4; mi++)
                af[mi] = *(const uint4*)&Ab[((abase + mi) * 4 + ks) * 128 + lane * 4];
#pragma unroll
            for (int ni = 0; ni < 4; ni++)
                bf[ni] = *(const uint2*)&Bb[((bbase + ni) * 4 + ks) * 64 + lane * 2];
#pragma unroll
            for (int mi = 0; mi < 4; mi++)
#pragma unroll
                for (int ni = 0; ni < 4; ni++)
                    mma_tf32(acc[mi][ni], af[mi], bf[ni]);

            // staged copy of next chunk, spread across ks steps:
            if (ks == 0 && stage) gm_ldg(Aptr, K, k1, tid, st);        // LDG A
            if (ks == 1 && stage) { gm_stA(An, st, tid);               // STS A
                                    gm_ldg(Bptr, K, k1, tid, st); }    // LDG B
            if (ks == 2 && stage) gm_stB(Bn, st, tid);                 // STS B
        }
        __syncthreads();
    }

    // epilogue: add bias, store (float2 per fragment row)
    int m_base = bm + warp_m * 64;
    int n_base = bn + warp_n * 32;
#pragma unroll
    for (int mi = 0; mi < 4; mi++) {
#pragma unroll
        for (int ni = 0; ni < 4; ni++) {
            int r0 = m_base + mi * 16 + g;
            int col = n_base + ni * 8 + t * 2;
            float b0 = __ldg(&bias[col]);
            float b1 = __ldg(&bias[col + 1]);
            float2 o0 = make_float2(acc[mi][ni][0] + b0, acc[mi][ni][1] + b1);
            float2 o1 = make_float2(acc[mi][ni][2] + b0, acc[mi][ni][3] + b1);
            *(float2*)&C[(size_t)r0 * N + col] = o0;
            *(float2*)&C[(size_t)(r0 + 8) * N + col] = o1;
        }
    }
}

// ---------------- causal attention (flash-style, online softmax) --------------
#define AT_TQ 16
#define AT_TS 64

__global__ __launch_bounds__(256) void attn_kernel(const float* __restrict__ q,
                                                   const float* __restrict__ k,
                                                   const float* __restrict__ v,
                                                   float* __restrict__ o) {
    int qt0 = blockIdx.x * AT_TQ;
    int h = blockIdx.y;
    int b = blockIdx.z;

    __shared__ float Qs[AT_TQ][DD + 1];
    __shared__ float Ks[AT_TS][DD + 1];
    __shared__ float Vs[AT_TS][DD + 1];
    __shared__ float Ps[AT_TQ][AT_TS + 1];
    __shared__ float m_s[AT_TQ], l_s[AT_TQ], alpha_s[AT_TQ];

    int tid = threadIdx.x;

    for (int i = tid; i < AT_TQ * DD; i += 256) {
        int r = i >> 6, d = i & 63;
        Qs[r][d] = q[(size_t)(b * TT + qt0 + r) * EE + h * DD + d];
    }
    if (tid < AT_TQ) { m_s[tid] = -1e30f; l_s[tid] = 0.0f; }
    __syncthreads();

    float o_acc[4] = {0.f, 0.f, 0.f, 0.f};
    int d_own = tid & 63;
    int r_base = (tid >> 6) * 4;

    int n_tiles = (qt0 + AT_TQ - 1) / AT_TS + 1;

    for (int kt = 0; kt < n_tiles; kt++) {
        int s0 = kt * AT_TS;
        for (int i = tid; i < AT_TS * DD; i += 256) {
            int r = i >> 6, d = i & 63;
            size_t gi = (size_t)(b * TT + s0 + r) * EE + h * DD + d;
            Ks[r][d] = k[gi];
            Vs[r][d] = v[gi];
        }
        __syncthreads();

        float sacc[4] = {0.f, 0.f, 0.f, 0.f};
#pragma unroll
        for (int d = 0; d < DD; d++) {
            float kv = Ks[d_own][d];
#pragma unroll
            for (int j = 0; j < 4; j++) sacc[j] = fmaf(Qs[r_base + j][d], kv, sacc[j]);
        }
        int s_glob = s0 + d_own;
#pragma unroll
        for (int j = 0; j < 4; j++) {
            int t_glob = qt0 + r_base + j;
            Ps[r_base + j][d_own] = (s_glob <= t_glob) ? sacc[j] : -1e30f;
        }
        __syncthreads();

        int warp = tid >> 5, lane = tid & 31;
#pragma unroll
        for (int rw = 0; rw < 2; rw++) {
            int rr = warp * 2 + rw;
            float x0 = Ps[rr][lane], x1 = Ps[rr][lane + 32];
            float mx = fmaxf(x0, x1);
#pragma unroll
            for (int off = 16; off; off >>= 1)
                mx = fmaxf(mx, __shfl_xor_sync(0xffffffffu, mx, off));
            float m_old = m_s[rr];
            float m_new = fmaxf(m_old, mx);
            float e0 = __expf(x0 - m_new);
            float e1 = __expf(x1 - m_new);
            float sum = e0 + e1;
#pragma unroll
            for (int off = 16; off; off >>= 1)
                sum += __shfl_xor_sync(0xffffffffu, sum, off);
            Ps[rr][lane] = e0;
            Ps[rr][lane + 32] = e1;
            if (lane == 0) {
                float alpha = __expf(m_old - m_new);
                alpha_s[rr] = alpha;
                l_s[rr] = l_s[rr] * alpha + sum;
                m_s[rr] = m_new;
            }
        }
        __syncthreads();

#pragma unroll
        for (int j = 0; j < 4; j++) o_acc[j] *= alpha_s[r_base + j];
#pragma unroll
        for (int s = 0; s < AT_TS; s++) {
            float vv = Vs[s][d_own];
#pragma unroll
            for (int j = 0; j < 4; j++) o_acc[j] = fmaf(Ps[r_base + j][s], vv, o_acc[j]);
        }
        __syncthreads();
    }

#pragma unroll
    for (int j = 0; j < 4; j++) {
        int r = r_base + j;
        o[(size_t)(b * TT + qt0 + r) * EE + h * DD + d_own] =
            o_acc[j] / l_s[r] * 0.125f;
    }
}

// ---------------- per-row logsumexp + per-row loss term -----------------------
__global__ __launch_bounds__(256) void lse_loss_kernel(const float* __restrict__ logits,
                                                       const int* __restrict__ targets,
                                                       float* __restrict__ lterms) {
    int row = blockIdx.x;
    const float* p = logits + (size_t)row * VV;
    float m = -1e30f, l = 0.0f;
    for (int i = threadIdx.x; i < VV; i += 256) {
        float x = p[i];
        if (x > m) { l = l * __expf(m - x) + 1.0f; m = x; }
        else       { l += __expf(x - m); }
    }
    __shared__ float ms[256], ls[256];
    ms[threadIdx.x] = m;
    ls[threadIdx.x] = l;
    __syncthreads();
    for (int s = 128; s; s >>= 1) {
        if (threadIdx.x < (unsigned)s) {
            float m2 = ms[threadIdx.x + s], l2 = ls[threadIdx.x + s];
            float M = fmaxf(ms[threadIdx.x], m2);
            ls[threadIdx.x] = ls[threadIdx.x] * __expf(ms[threadIdx.x] - M) + l2 * __expf(m2 - M);
            ms[threadIdx.x] = M;
        }
        __syncthreads();
    }
    if (threadIdx.x == 0) {
        float lse = ms[0] + logf(ls[0]);
        lterms[row] = lse - p[targets[row]];
    }
}

__global__ __launch_bounds__(256) void loss_reduce(const float* __restrict__ lterms,
                                                   float* __restrict__ out, int do_write) {
    __shared__ float s[256];
    float acc = 0.0f;
    for (int i = threadIdx.x; i < BT; i += 256) acc += lterms[i];
    s[threadIdx.x] = acc;
    __syncthreads();
    for (int st = 128; st; st >>= 1) {
        if (threadIdx.x < (unsigned)st) s[threadIdx.x] += s[threadIdx.x + st];
        __syncthreads();
    }
    if (threadIdx.x == 0 && do_write) out[0] = s[0] / (float)BT;
}

// ------------------------------- launch ---------------------------------------
#define GSM_BYTES (4 * GM_BUF * sizeof(float))   // 64KB dynamic smem

extern "C" void kernel_launch(void* const* d_in, const int* in_sizes, int n_in,
                              void* d_out, int out_size) {
    const int*   tokens    = (const int*)d_in[0];
    const int*   targets   = (const int*)d_in[1];
    const float* tok_table = (const float*)d_in[2];
    const float* pos_emb   = (const float*)d_in[3];
    const float* Wq        = (const float*)d_in[4];
    const float* bq        = (const float*)d_in[5];
    const float* Wk        = (const float*)d_in[6];
    const float* bk        = (const float*)d_in[7];
    const float* Wv        = (const float*)d_in[8];
    const float* bv        = (const float*)d_in[9];
    const float* Wo        = (const float*)d_in[10];
    const float* bo        = (const float*)d_in[11];
    float* out = (float*)d_out;

    float *x, *q, *k, *v, *o, *lt;
    cudaGetSymbolAddress((void**)&x,  g_x);
    cudaGetSymbolAddress((void**)&q,  g_q);
    cudaGetSymbolAddress((void**)&k,  g_k);
    cudaGetSymbolAddress((void**)&v,  g_v);
    cudaGetSymbolAddress((void**)&o,  g_o);
    cudaGetSymbolAddress((void**)&lt, g_lterms);

    static int smem_set = 0;
    if (!smem_set) {
        cudaFuncSetAttribute(gemm_mma, cudaFuncAttributeMaxDynamicSharedMemorySize,
                             (int)GSM_BYTES);
        smem_set = 1;
    }

    // 1) embedding
    embed_kernel<<<(BT * EE) / 256, 256>>>(tokens, tok_table, pos_emb, x);

    // 2) QKV projections (tf32 mma.sync NT gemms, N=E)
    dim3 gqkv(BT / GM_BM, EE / GM_BN);   // m fastest
    gemm_mma<<<gqkv, 256, GSM_BYTES>>>(x, Wq, bq, q, BT, EE, EE);
    gemm_mma<<<gqkv, 256, GSM_BYTES>>>(x, Wk, bk, k, BT, EE, EE);
    gemm_mma<<<gqkv, 256, GSM_BYTES>>>(x, Wv, bv, v, BT, EE, EE);

    // 3) causal attention
    attn_kernel<<<dim3(TT / AT_TQ, HH, BB), 256>>>(q, k, v, o);

    // 4) output projection -> logits straight into d_out
    dim3 glog(BT / GM_BM, VV / GM_BN);   // m fastest: Wo tile stays L2-resident
    gemm_mma<<<glog, 256, GSM_BYTES>>>(o, Wo, bo, out, BT, VV, EE);

    // 5) loss
    lse_loss_kernel<<<BT, 256>>>(out, targets, lt);
    int write_loss = (out_size > BT * VV) ? 1 : 0;
    loss_reduce<<<1, 256>>>(lt, out + (size_t)BT * VV, write_loss);
}

// round 10
// speedup vs baseline: 1.8405x; 1.6144x over previous
#include <cuda_runtime.h>
#include <cuda_fp16.h>
#include <cuda_bf16.h>
#include <cstdint>
#include <math.h>

// Problem constants
#define BB 2
#define TT 2048
#define EE 1024
#define HH 16
#define DD 64
#define VV 32000
#define BT (BB * TT)   // 4096

// ---------------- scratch (device globals; no allocations allowed) ------------
__device__ float g_x[BT * EE];
__device__ float g_q[BT * EE];
__device__ float g_k[BT * EE];
__device__ float g_v[BT * EE];
__device__ float g_o[BT * EE];
__device__ float g_lterms[BT];

// ---------------- helpers -----------------------------------------------------
__device__ __forceinline__ uint32_t pack_h2(float lo, float hi) {
    __half2 h = __floats2half2_rn(lo, hi);   // lo -> .x (low 16 bits)
    return *(uint32_t*)&h;
}

// fp16 m16n8k16, fp32 accumulate
__device__ __forceinline__ void mma_f16(float* d, const uint4& a, const uint2& b) {
    asm volatile(
        "mma.sync.aligned.m16n8k16.row.col.f32.f16.f16.f32 "
        "{%0,%1,%2,%3}, {%4,%5,%6,%7}, {%8,%9}, {%0,%1,%2,%3};"
        : "+f"(d[0]), "+f"(d[1]), "+f"(d[2]), "+f"(d[3])
        : "r"(a.x), "r"(a.y), "r"(a.z), "r"(a.w), "r"(b.x), "r"(b.y));
}

// ---------------- embedding: x = tok_table[tokens] + pos_emb ------------------
__global__ void embed_kernel(const int* __restrict__ tokens,
                             const float* __restrict__ tok_table,
                             const float* __restrict__ pos_emb,
                             float* __restrict__ x) {
    int idx = blockIdx.x * blockDim.x + threadIdx.x;  // over BT*EE
    int bt = idx >> 10;          // /EE
    int e  = idx & (EE - 1);
    int t  = bt & (TT - 1);      // bt % TT
    int tok = tokens[bt];
    x[idx] = tok_table[tok * EE + e] + pos_emb[t * EE + e];
}

// ====== mma.sync fp16 NT GEMM: C[m,n] = sum_k A[m,k]B[n,k] + bias[n] ==========
// CTA tile 128x128, BK=32 (2 k-steps of 16). 256 threads, 8 warps (2x4),
// warp tile 64x32 = 4x4 m16n8k16 fragments. fp32 accumulate in registers.
// 2 CTAs/SM. Inputs converted fp32 -> fp16 (RN) at the STS stage.
//
// SMEM (fragment-native uint32 arrays, conflict-free):
//   As: [R=8 (16-row blk)][ks=2][lane=32][4]   (2048 u32 = 8KB per buffer)
//   Bs: [Nb=16 (8-col blk)][ks=2][lane=32][2]  (2048 u32 = 8KB per buffer)
// Fragment mapping (lane = g*4+t):
//   A reg r: r0=(g, 2t..2t+1 | k<8), r1=(g+8, same), r2=(g, 2t+8..9), r3=(g+8, same)
//   B reg r: r0=(k=2t..2t+1, n=g), r1=(k=2t+8..9, n=g)

#define GM_BM 128
#define GM_BN 128
#define GM_BK 32
#define GM_BUF 2048     // uint32 per As or Bs buffer

__device__ __forceinline__ void gm_ldg(const float* __restrict__ P, int K, int k0,
                                       int tid, float4* p) {
#pragma unroll
    for (int it = 0; it < 4; it++) {
        int q = tid + it * 256;
        int row = q >> 3, c = q & 7;
        p[it] = *(const float4*)(P + (size_t)row * K + k0 + c * 4);
    }
}

__device__ __forceinline__ void gm_stA(uint32_t* __restrict__ As, const float4* p, int tid) {
#pragma unroll
    for (int it = 0; it < 4; it++) {
        int q = tid + it * 256;
        int row = q >> 3, c = q & 7;
        int ks = c >> 2;                 // 0..1 (k16 step)
        int kk = (c & 3) << 2;           // 0,4,8,12 within k16
        int rh = kk >> 3;                // 0: regs 0/1, 1: regs 2/3
        int tp = (kk & 7) >> 1;          // thread pair base 0 or 2
        int R = row >> 4, r16 = row & 15;
        int g = r16 & 7, hi = r16 >> 3;
        int reg = rh * 2 + hi;
        int base = ((R * 2 + ks) * 32 + g * 4);
        As[(base + tp + 0) * 4 + reg] = pack_h2(p[it].x, p[it].y);
        As[(base + tp + 1) * 4 + reg] = pack_h2(p[it].z, p[it].w);
    }
}

__device__ __forceinline__ void gm_stB(uint32_t* __restrict__ Bs, const float4* p, int tid) {
#pragma unroll
    for (int it = 0; it < 4; it++) {
        int q = tid + it * 256;
        int row = q >> 3, c = q & 7;
        int ks = c >> 2;
        int kk = (c & 3) << 2;
        int reg = kk >> 3;               // b0 (k<8) or b1 (k>=8)
        int tp = (kk & 7) >> 1;
        int Nb = row >> 3, gn = row & 7;
        int base = ((Nb * 2 + ks) * 32 + gn * 4);
        Bs[(base + tp + 0) * 2 + reg] = pack_h2(p[it].x, p[it].y);
        Bs[(base + tp + 1) * 2 + reg] = pack_h2(p[it].z, p[it].w);
    }
}

__global__ __launch_bounds__(256, 2) void gemm_mma(const float* __restrict__ A,
                                                   const float* __restrict__ B,
                                                   const float* __restrict__ bias,
                                                   float* __restrict__ C,
                                                   int M, int N, int K) {
    extern __shared__ uint32_t sm[];
    uint32_t* As = sm;              // [2][GM_BUF]
    uint32_t* Bs = sm + 2 * GM_BUF;

    int tid = threadIdx.x;
    int lane = tid & 31, wid = tid >> 5;
    int warp_m = wid >> 2, warp_n = wid & 3;
    int g = lane >> 2, t = lane & 3;

    int bm = blockIdx.x * GM_BM;
    int bn = blockIdx.y * GM_BN;

    const float* Aptr = A + (size_t)bm * K;
    const float* Bptr = B + (size_t)bn * K;

    float acc[4][4][4];
#pragma unroll
    for (int mi = 0; mi < 4; mi++)
#pragma unroll
        for (int ni = 0; ni < 4; ni++)
#pragma unroll
            for (int e = 0; e < 4; e++) acc[mi][ni][e] = 0.0f;

    const int NCH = K / GM_BK;
    int abase = warp_m * 4;    // R offset
    int bbase = warp_n * 4;    // Nb offset

    float4 st[4];              // single staging array (A then B)
    gm_ldg(Aptr, K, 0, tid, st);
    gm_stA(As, st, tid);
    gm_ldg(Bptr, K, 0, tid, st);
    gm_stB(Bs, st, tid);
    __syncthreads();

    for (int i = 0; i < NCH; i++) {
        int buf = i & 1;
        uint32_t* An = As + (buf ^ 1) * GM_BUF;
        uint32_t* Bn = Bs + (buf ^ 1) * GM_BUF;
        const uint32_t* Ab = As + buf * GM_BUF;
        const uint32_t* Bb = Bs + buf * GM_BUF;
        bool stage = (i + 1 < NCH);
        int k1 = (i + 1) * GM_BK;

#pragma unroll
        for (int ks = 0; ks < 2; ks++) {
            uint4 af[4];
            uint2 bf[4];
#pragma unroll
            for (int mi = 0; mi < 4; mi++)
                af[mi] = *(const uint4*)&Ab[(((abase + mi) * 2 + ks) * 32 + lane) * 4];
#pragma unroll
            for (int ni = 0; ni < 4; ni++)
                bf[ni] = *(const uint2*)&Bb[(((bbase + ni) * 2 + ks) * 32 + lane) * 2];
#pragma unroll
            for (int mi = 0; mi < 4; mi++)
#pragma unroll
                for (int ni = 0; ni < 4; ni++)
                    mma_f16(acc[mi][ni], af[mi], bf[ni]);

            // staged copy of next chunk spread across the two ks steps
            if (ks == 0 && stage) { gm_ldg(Aptr, K, k1, tid, st);
                                    gm_stA(An, st, tid);
                                    gm_ldg(Bptr, K, k1, tid, st); }
            if (ks == 1 && stage)   gm_stB(Bn, st, tid);
        }
        __syncthreads();
    }

    // epilogue: add bias, store (float2 per fragment row)
    int m_base = bm + warp_m * 64;
    int n_base = bn + warp_n * 32;
#pragma unroll
    for (int mi = 0; mi < 4; mi++) {
#pragma unroll
        for (int ni = 0; ni < 4; ni++) {
            int r0 = m_base + mi * 16 + g;
            int col = n_base + ni * 8 + t * 2;
            float b0 = __ldg(&bias[col]);
            float b1 = __ldg(&bias[col + 1]);
            float2 o0 = make_float2(acc[mi][ni][0] + b0, acc[mi][ni][1] + b1);
            float2 o1 = make_float2(acc[mi][ni][2] + b0, acc[mi][ni][3] + b1);
            *(float2*)&C[(size_t)r0 * N + col] = o0;
            *(float2*)&C[(size_t)(r0 + 8) * N + col] = o1;
        }
    }
}

// ---------------- causal attention (flash-style, online softmax) --------------
#define AT_TQ 16
#define AT_TS 64

__global__ __launch_bounds__(256) void attn_kernel(const float* __restrict__ q,
                                                   const float* __restrict__ k,
                                                   const float* __restrict__ v,
                                                   float* __restrict__ o) {
    int qt0 = blockIdx.x * AT_TQ;
    int h = blockIdx.y;
    int b = blockIdx.z;

    __shared__ float Qs[AT_TQ][DD + 1];
    __shared__ float Ks[AT_TS][DD + 1];
    __shared__ float Vs[AT_TS][DD + 1];
    __shared__ float Ps[AT_TQ][AT_TS + 1];
    __shared__ float m_s[AT_TQ], l_s[AT_TQ], alpha_s[AT_TQ];

    int tid = threadIdx.x;

    for (int i = tid; i < AT_TQ * DD; i += 256) {
        int r = i >> 6, d = i & 63;
        Qs[r][d] = q[(size_t)(b * TT + qt0 + r) * EE + h * DD + d];
    }
    if (tid < AT_TQ) { m_s[tid] = -1e30f; l_s[tid] = 0.0f; }
    __syncthreads();

    float o_acc[4] = {0.f, 0.f, 0.f, 0.f};
    int d_own = tid & 63;
    int r_base = (tid >> 6) * 4;

    int n_tiles = (qt0 + AT_TQ - 1) / AT_TS + 1;

    for (int kt = 0; kt < n_tiles; kt++) {
        int s0 = kt * AT_TS;
        for (int i = tid; i < AT_TS * DD; i += 256) {
            int r = i >> 6, d = i & 63;
            size_t gi = (size_t)(b * TT + s0 + r) * EE + h * DD + d;
            Ks[r][d] = k[gi];
            Vs[r][d] = v[gi];
        }
        __syncthreads();

        float sacc[4] = {0.f, 0.f, 0.f, 0.f};
#pragma unroll
        for (int d = 0; d < DD; d++) {
            float kv = Ks[d_own][d];
#pragma unroll
            for (int j = 0; j < 4; j++) sacc[j] = fmaf(Qs[r_base + j][d], kv, sacc[j]);
        }
        int s_glob = s0 + d_own;
#pragma unroll
        for (int j = 0; j < 4; j++) {
            int t_glob = qt0 + r_base + j;
            Ps[r_base + j][d_own] = (s_glob <= t_glob) ? sacc[j] : -1e30f;
        }
        __syncthreads();

        int warp = tid >> 5, lane = tid & 31;
#pragma unroll
        for (int rw = 0; rw < 2; rw++) {
            int rr = warp * 2 + rw;
            float x0 = Ps[rr][lane], x1 = Ps[rr][lane + 32];
            float mx = fmaxf(x0, x1);
#pragma unroll
            for (int off = 16; off; off >>= 1)
                mx = fmaxf(mx, __shfl_xor_sync(0xffffffffu, mx, off));
            float m_old = m_s[rr];
            float m_new = fmaxf(m_old, mx);
            float e0 = __expf(x0 - m_new);
            float e1 = __expf(x1 - m_new);
            float sum = e0 + e1;
#pragma unroll
            for (int off = 16; off; off >>= 1)
                sum += __shfl_xor_sync(0xffffffffu, sum, off);
            Ps[rr][lane] = e0;
            Ps[rr][lane + 32] = e1;
            if (lane == 0) {
                float alpha = __expf(m_old - m_new);
                alpha_s[rr] = alpha;
                l_s[rr] = l_s[rr] * alpha + sum;
                m_s[rr] = m_new;
            }
        }
        __syncthreads();

#pragma unroll
        for (int j = 0; j < 4; j++) o_acc[j] *= alpha_s[r_base + j];
#pragma unroll
        for (int s = 0; s < AT_TS; s++) {
            float vv = Vs[s][d_own];
#pragma unroll
            for (int j = 0; j < 4; j++) o_acc[j] = fmaf(Ps[r_base + j][s], vv, o_acc[j]);
        }
        __syncthreads();
    }

#pragma unroll
    for (int j = 0; j < 4; j++) {
        int r = r_base + j;
        o[(size_t)(b * TT + qt0 + r) * EE + h * DD + d_own] =
            o_acc[j] / l_s[r] * 0.125f;
    }
}

// ---------------- per-row logsumexp + per-row loss term -----------------------
__global__ __launch_bounds__(256) void lse_loss_kernel(const float* __restrict__ logits,
                                                       const int* __restrict__ targets,
                                                       float* __restrict__ lterms) {
    int row = blockIdx.x;
    const float* p = logits + (size_t)row * VV;
    float m = -1e30f, l = 0.0f;
    for (int i = threadIdx.x; i < VV; i += 256) {
        float x = p[i];
        if (x > m) { l = l * __expf(m - x) + 1.0f; m = x; }
        else       { l += __expf(x - m); }
    }
    __shared__ float ms[256], ls[256];
    ms[threadIdx.x] = m;
    ls[threadIdx.x] = l;
    __syncthreads();
    for (int s = 128; s; s >>= 1) {
        if (threadIdx.x < (unsigned)s) {
            float m2 = ms[threadIdx.x + s], l2 = ls[threadIdx.x + s];
            float M = fmaxf(ms[threadIdx.x], m2);
            ls[threadIdx.x] = ls[threadIdx.x] * __expf(ms[threadIdx.x] - M) + l2 * __expf(m2 - M);
            ms[threadIdx.x] = M;
        }
        __syncthreads();
    }
    if (threadIdx.x == 0) {
        float lse = ms[0] + logf(ls[0]);
        lterms[row] = lse - p[targets[row]];
    }
}

__global__ __launch_bounds__(256) void loss_reduce(const float* __restrict__ lterms,
                                                   float* __restrict__ out, int do_write) {
    __shared__ float s[256];
    float acc = 0.0f;
    for (int i = threadIdx.x; i < BT; i += 256) acc += lterms[i];
    s[threadIdx.x] = acc;
    __syncthreads();
    for (int st = 128; st; st >>= 1) {
        if (threadIdx.x < (unsigned)st) s[threadIdx.x] += s[threadIdx.x + st];
        __syncthreads();
    }
    if (threadIdx.x == 0 && do_write) out[0] = s[0] / (float)BT;
}

// ------------------------------- launch ---------------------------------------
#define GSM_BYTES (4 * GM_BUF * sizeof(uint32_t))   // 32KB dynamic smem

extern "C" void kernel_launch(void* const* d_in, const int* in_sizes, int n_in,
                              void* d_out, int out_size) {
    const int*   tokens    = (const int*)d_in[0];
    const int*   targets   = (const int*)d_in[1];
    const float* tok_table = (const float*)d_in[2];
    const float* pos_emb   = (const float*)d_in[3];
    const float* Wq        = (const float*)d_in[4];
    const float* bq        = (const float*)d_in[5];
    const float* Wk        = (const float*)d_in[6];
    const float* bk        = (const float*)d_in[7];
    const float* Wv        = (const float*)d_in[8];
    const float* bv        = (const float*)d_in[9];
    const float* Wo        = (const float*)d_in[10];
    const float* bo        = (const float*)d_in[11];
    float* out = (float*)d_out;

    float *x, *q, *k, *v, *o, *lt;
    cudaGetSymbolAddress((void**)&x,  g_x);
    cudaGetSymbolAddress((void**)&q,  g_q);
    cudaGetSymbolAddress((void**)&k,  g_k);
    cudaGetSymbolAddress((void**)&v,  g_v);
    cudaGetSymbolAddress((void**)&o,  g_o);
    cudaGetSymbolAddress((void**)&lt, g_lterms);

    static int smem_set = 0;
    if (!smem_set) {
        cudaFuncSetAttribute(gemm_mma, cudaFuncAttributeMaxDynamicSharedMemorySize,
                             (int)GSM_BYTES);
        smem_set = 1;
    }

    // 1) embedding
    embed_kernel<<<(BT * EE) / 256, 256>>>(tokens, tok_table, pos_emb, x);

    // 2) QKV projections (fp16 mma.sync NT gemms, N=E)
    dim3 gqkv(BT / GM_BM, EE / GM_BN);   // m fastest
    gemm_mma<<<gqkv, 256, GSM_BYTES>>>(x, Wq, bq, q, BT, EE, EE);
    gemm_mma<<<gqkv, 256, GSM_BYTES>>>(x, Wk, bk, k, BT, EE, EE);
    gemm_mma<<<gqkv, 256, GSM_BYTES>>>(x, Wv, bv, v, BT, EE, EE);

    // 3) causal attention
    attn_kernel<<<dim3(TT / AT_TQ, HH, BB), 256>>>(q, k, v, o);

    // 4) output projection -> logits straight into d_out
    dim3 glog(BT / GM_BM, VV / GM_BN);   // m fastest: Wo tile stays L2-resident
    gemm_mma<<<glog, 256, GSM_BYTES>>>(o, Wo, bo, out, BT, VV, EE);

    // 5) loss
    lse_loss_kernel<<<BT, 256>>>(out, targets, lt);
    int write_loss = (out_size > BT * VV) ? 1 : 0;
    loss_reduce<<<1, 256>>>(lt, out + (size_t)BT * VV, write_loss);
}